// round 2
// baseline (speedup 1.0000x reference)
#include <cuda_runtime.h>
#include <cstddef>

#define BB 512
#define TT 200
#define SI 100
#define DI 68
#define HS 256
#define HD 128
#define NN 10000
#define DDIM 512   // 2*HD + HS

// ---------------- scratch (static device arrays; no runtime allocation) ----------------
__device__ float g_s[BB * HS];                 // static branch output [B,HS]
__device__ float g_xwf[BB * TT * HD];          // xw fwd -> overwritten by fwd hidden states
__device__ float g_xwb[BB * TT * HD];          // xw bwd -> overwritten by bwd hidden states
__device__ float g_cs[BB];                     // per-trial static dot + bias
__device__ float g_wdyn_t[DI * HD];            // w_dyn transposed [k][o]
__device__ float g_wihf_t[HD * HD];            // w_ih_f transposed [k][o]
__device__ float g_wihb_t[HD * HD];
__device__ float g_whhf_t[HD * HD];            // w_hh_f transposed [k][o]
__device__ float g_whhb_t[HD * HD];
__device__ float g_bxf[HD];                    // b_ih_f + b_hh_f
__device__ float g_bxb[HD];

// ---------------- prep: transposes + bias folds ----------------
__global__ void prep_kernel(const float* __restrict__ w_dyn,
                            const float* __restrict__ w_ih_f,
                            const float* __restrict__ w_hh_f,
                            const float* __restrict__ w_ih_b,
                            const float* __restrict__ w_hh_b,
                            const float* __restrict__ b_ih_f,
                            const float* __restrict__ b_hh_f,
                            const float* __restrict__ b_ih_b,
                            const float* __restrict__ b_hh_b) {
    int idx = blockIdx.x * blockDim.x + threadIdx.x;
    if (idx < HD * HD) {
        int o = idx / HD, k = idx % HD;
        g_wihf_t[k * HD + o] = w_ih_f[idx];
        g_wihb_t[k * HD + o] = w_ih_b[idx];
        g_whhf_t[k * HD + o] = w_hh_f[idx];
        g_whhb_t[k * HD + o] = w_hh_b[idx];
    }
    if (idx < HD * DI) {               // w_dyn is [HD,DI] row-major
        int o = idx / DI, i = idx % DI;
        g_wdyn_t[i * HD + o] = w_dyn[idx];
    }
    if (idx < HD) {
        g_bxf[idx] = b_ih_f[idx] + b_hh_f[idx];
        g_bxb[idx] = b_ih_b[idx] + b_hh_b[idx];
    }
}

// ---------------- static branch: 2-layer MLP, one block per trial ----------------
__global__ void static_kernel(const float* __restrict__ xs,
                              const float* __restrict__ w1, const float* __restrict__ b1,
                              const float* __restrict__ w2, const float* __restrict__ b2) {
    int b = blockIdx.x;
    int j = threadIdx.x;                // 256 threads, one per hidden unit
    __shared__ float xsh[SI];
    __shared__ float s1[HS];
    if (j < SI) xsh[j] = xs[b * SI + j];
    __syncthreads();
    float acc = b1[j];
    #pragma unroll 4
    for (int i = 0; i < SI; i++) acc += xsh[i] * w1[j * SI + i];
    s1[j] = fmaxf(acc, 0.f);
    __syncthreads();
    acc = b2[j];
    #pragma unroll 4
    for (int i = 0; i < HS; i++) acc += s1[i] * w2[j * HS + i];
    g_s[b * HS + j] = fmaxf(acc, 0.f);
}

// ---------------- fused: d = relu(x_dyn @ Wdyn^T + b); xw_{f,b} = d @ Wih^T + bx ----------------
// 256 threads = 8 warps; each warp independently owns 4 rows (b*T+t).
// Lane computes 4 rows x 4 output cols (cols 4*lane..4*lane+3). No block barriers.
__global__ void __launch_bounds__(256) fused_gemm_kernel(const float* __restrict__ xd,
                                                         const float* __restrict__ bdyn) {
    __shared__ float xs[8][4 * DI];        // per-warp x rows (4 x 68)
    __shared__ float ds[8][4][HD];         // per-warp d rows (4 x 128)
    int w = threadIdx.x >> 5, lane = threadIdx.x & 31;
    size_t row0 = ((size_t)blockIdx.x * 8 + w) * 4;     // grid = 102400/32 = 3200

    // load 4 x rows (272 floats) cooperatively within warp
    const float* src = xd + row0 * DI;
    for (int i = lane; i < 4 * DI; i += 32) xs[w][i] = src[i];
    __syncwarp();

    // ---- stage 1: d tile ----
    {
        float4 bv = *(const float4*)&bdyn[4 * lane];
        float4 a0 = bv, a1 = bv, a2 = bv, a3 = bv;
        #pragma unroll 4
        for (int k = 0; k < DI; k++) {
            float4 wv = *(const float4*)&g_wdyn_t[k * HD + 4 * lane];
            float x0 = xs[w][0 * DI + k];
            float x1 = xs[w][1 * DI + k];
            float x2 = xs[w][2 * DI + k];
            float x3 = xs[w][3 * DI + k];
            a0.x += x0 * wv.x; a0.y += x0 * wv.y; a0.z += x0 * wv.z; a0.w += x0 * wv.w;
            a1.x += x1 * wv.x; a1.y += x1 * wv.y; a1.z += x1 * wv.z; a1.w += x1 * wv.w;
            a2.x += x2 * wv.x; a2.y += x2 * wv.y; a2.z += x2 * wv.z; a2.w += x2 * wv.w;
            a3.x += x3 * wv.x; a3.y += x3 * wv.y; a3.z += x3 * wv.z; a3.w += x3 * wv.w;
        }
        a0.x = fmaxf(a0.x, 0.f); a0.y = fmaxf(a0.y, 0.f); a0.z = fmaxf(a0.z, 0.f); a0.w = fmaxf(a0.w, 0.f);
        a1.x = fmaxf(a1.x, 0.f); a1.y = fmaxf(a1.y, 0.f); a1.z = fmaxf(a1.z, 0.f); a1.w = fmaxf(a1.w, 0.f);
        a2.x = fmaxf(a2.x, 0.f); a2.y = fmaxf(a2.y, 0.f); a2.z = fmaxf(a2.z, 0.f); a2.w = fmaxf(a2.w, 0.f);
        a3.x = fmaxf(a3.x, 0.f); a3.y = fmaxf(a3.y, 0.f); a3.z = fmaxf(a3.z, 0.f); a3.w = fmaxf(a3.w, 0.f);
        *(float4*)&ds[w][0][4 * lane] = a0;
        *(float4*)&ds[w][1][4 * lane] = a1;
        *(float4*)&ds[w][2][4 * lane] = a2;
        *(float4*)&ds[w][3][4 * lane] = a3;
    }
    __syncwarp();

    // ---- stage 2: dual GEMM over k=128 ----
    float4 bf4 = *(const float4*)&g_bxf[4 * lane];
    float4 bb4 = *(const float4*)&g_bxb[4 * lane];
    float4 f0 = bf4, f1 = bf4, f2 = bf4, f3 = bf4;
    float4 g0 = bb4, g1 = bb4, g2 = bb4, g3 = bb4;

    #pragma unroll 2
    for (int k = 0; k < HD; k += 4) {
        float4 d0 = *(const float4*)&ds[w][0][k];
        float4 d1 = *(const float4*)&ds[w][1][k];
        float4 d2 = *(const float4*)&ds[w][2][k];
        float4 d3 = *(const float4*)&ds[w][3][k];
        #pragma unroll
        for (int kk = 0; kk < 4; kk++) {
            float4 wf = *(const float4*)&g_wihf_t[(k + kk) * HD + 4 * lane];
            float4 wb = *(const float4*)&g_wihb_t[(k + kk) * HD + 4 * lane];
            float v0 = (kk == 0) ? d0.x : (kk == 1) ? d0.y : (kk == 2) ? d0.z : d0.w;
            float v1 = (kk == 0) ? d1.x : (kk == 1) ? d1.y : (kk == 2) ? d1.z : d1.w;
            float v2 = (kk == 0) ? d2.x : (kk == 1) ? d2.y : (kk == 2) ? d2.z : d2.w;
            float v3 = (kk == 0) ? d3.x : (kk == 1) ? d3.y : (kk == 2) ? d3.z : d3.w;
            f0.x += v0 * wf.x; f0.y += v0 * wf.y; f0.z += v0 * wf.z; f0.w += v0 * wf.w;
            f1.x += v1 * wf.x; f1.y += v1 * wf.y; f1.z += v1 * wf.z; f1.w += v1 * wf.w;
            f2.x += v2 * wf.x; f2.y += v2 * wf.y; f2.z += v2 * wf.z; f2.w += v2 * wf.w;
            f3.x += v3 * wf.x; f3.y += v3 * wf.y; f3.z += v3 * wf.z; f3.w += v3 * wf.w;
            g0.x += v0 * wb.x; g0.y += v0 * wb.y; g0.z += v0 * wb.z; g0.w += v0 * wb.w;
            g1.x += v1 * wb.x; g1.y += v1 * wb.y; g1.z += v1 * wb.z; g1.w += v1 * wb.w;
            g2.x += v2 * wb.x; g2.y += v2 * wb.y; g2.z += v2 * wb.z; g2.w += v2 * wb.w;
            g3.x += v3 * wb.x; g3.y += v3 * wb.y; g3.z += v3 * wb.z; g3.w += v3 * wb.w;
        }
    }

    size_t obase = row0 * HD + 4 * lane;
    *(float4*)&g_xwf[obase + 0 * HD] = f0;
    *(float4*)&g_xwf[obase + 1 * HD] = f1;
    *(float4*)&g_xwf[obase + 2 * HD] = f2;
    *(float4*)&g_xwf[obase + 3 * HD] = f3;
    *(float4*)&g_xwb[obase + 0 * HD] = g0;
    *(float4*)&g_xwb[obase + 1 * HD] = g1;
    *(float4*)&g_xwb[obase + 2 * HD] = g2;
    *(float4*)&g_xwb[obase + 3 * HD] = g3;
}

// ---------------- RNN scan: warp-autonomous. 1 warp = 1 (trial, dir). ----------------
// h lives in a per-warp smem row; lane owns output cols 4*lane..4*lane+3.
// No __syncthreads — only __syncwarp. W stays hot in L1 (64KB/dir).
__global__ void __launch_bounds__(128) rnn_scan_kernel() {
    __shared__ float h_sm[4][HD];
    int w = threadIdx.x >> 5, lane = threadIdx.x & 31;
    int wg = blockIdx.x * 4 + w;                 // 0..1023
    int trial = wg & 511;
    int dir = wg >> 9;
    const float* __restrict__ W = dir ? g_whhb_t : g_whhf_t;
    float* __restrict__ xw = (dir ? g_xwb : g_xwf) + (size_t)trial * TT * HD;
    float* hrow = h_sm[w];

    *(float4*)&hrow[4 * lane] = make_float4(0.f, 0.f, 0.f, 0.f);
    __syncwarp();

    for (int step = 0; step < TT; ++step) {
        int t = dir ? (TT - 1 - step) : step;
        float* xwt = xw + t * HD;
        float4 acc = *(const float4*)&xwt[4 * lane];

        #pragma unroll 8
        for (int k = 0; k < HD; k += 4) {
            float4 hv = *(const float4*)&hrow[k];
            float4 w0 = *(const float4*)&W[(k + 0) * HD + 4 * lane];
            float4 w1 = *(const float4*)&W[(k + 1) * HD + 4 * lane];
            float4 w2 = *(const float4*)&W[(k + 2) * HD + 4 * lane];
            float4 w3 = *(const float4*)&W[(k + 3) * HD + 4 * lane];
            acc.x += hv.x * w0.x + hv.y * w1.x + hv.z * w2.x + hv.w * w3.x;
            acc.y += hv.x * w0.y + hv.y * w1.y + hv.z * w2.y + hv.w * w3.y;
            acc.z += hv.x * w0.z + hv.y * w1.z + hv.z * w2.z + hv.w * w3.z;
            acc.w += hv.x * w0.w + hv.y * w1.w + hv.z * w2.w + hv.w * w3.w;
        }
        acc.x = fmaxf(acc.x, 0.f);
        acc.y = fmaxf(acc.y, 0.f);
        acc.z = fmaxf(acc.z, 0.f);
        acc.w = fmaxf(acc.w, 0.f);
        __syncwarp();                    // all reads of old h done
        *(float4*)&hrow[4 * lane] = acc;
        *(float4*)&xwt[4 * lane] = acc;  // in-place: becomes the RNN output
        __syncwarp();                    // new h visible before next step
    }
}

// ---------------- c_s[b] = <s[b], Wn[:256]> + bn ----------------
__global__ void cs_kernel(const int* __restrict__ order,
                          const float* __restrict__ nw,
                          const float* __restrict__ nb) {
    int b = blockIdx.x;
    int tid = threadIdx.x;               // 256
    int n = order[b];
    float v = g_s[b * HS + tid] * nw[(size_t)n * DDIM + tid];
    #pragma unroll
    for (int s = 16; s > 0; s >>= 1) v += __shfl_down_sync(0xffffffffu, v, s);
    __shared__ float partial[8];
    if ((tid & 31) == 0) partial[tid >> 5] = v;
    __syncthreads();
    if (tid == 0) {
        float sum = 0.f;
        #pragma unroll
        for (int i = 0; i < 8; i++) sum += partial[i];
        g_cs[b] = sum + nb[n];
    }
}

// ---------------- out[b,t] = relu(c_s[b] + <fwd, Wn[256:384]> + <bwd, Wn[384:512]>) ----------------
__global__ void out_kernel(const int* __restrict__ order,
                           const float* __restrict__ nw,
                           float* __restrict__ out) {
    int b = blockIdx.x;
    int tid = threadIdx.x;               // 256 = 8 warps
    int n = order[b];
    __shared__ float4 wsh[64];           // 256 floats: dynamic part of Wn
    if (tid < 64) wsh[tid] = *(const float4*)&nw[(size_t)n * DDIM + HS + 4 * tid];
    __syncthreads();
    float cs = g_cs[b];
    int w = tid >> 5, lane = tid & 31;
    float4 wf = wsh[lane];
    float4 wb = wsh[32 + lane];
    #pragma unroll 5
    for (int i = 0; i < 25; i++) {
        int t = w + 8 * i;
        size_t base = ((size_t)b * TT + t) * HD + 4 * lane;
        float4 fv = *(const float4*)&g_xwf[base];
        float4 bv = *(const float4*)&g_xwb[base];
        float acc = fv.x * wf.x + fv.y * wf.y + fv.z * wf.z + fv.w * wf.w
                  + bv.x * wb.x + bv.y * wb.y + bv.z * wb.z + bv.w * wb.w;
        #pragma unroll
        for (int s = 16; s > 0; s >>= 1) acc += __shfl_down_sync(0xffffffffu, acc, s);
        if (lane == 0) out[b * TT + t] = fmaxf(acc + cs, 0.f);
    }
}

// ---------------- launch ----------------
extern "C" void kernel_launch(void* const* d_in, const int* in_sizes, int n_in,
                              void* d_out, int out_size) {
    const float* x_static  = (const float*)d_in[0];
    const float* x_dynamic = (const float*)d_in[1];
    const int*   order     = (const int*)  d_in[2];
    const float* w_s1      = (const float*)d_in[3];
    const float* b_s1      = (const float*)d_in[4];
    const float* w_s2      = (const float*)d_in[5];
    const float* b_s2      = (const float*)d_in[6];
    const float* w_dyn     = (const float*)d_in[7];
    const float* b_dyn     = (const float*)d_in[8];
    const float* w_ih_f    = (const float*)d_in[9];
    const float* w_hh_f    = (const float*)d_in[10];
    const float* b_ih_f    = (const float*)d_in[11];
    const float* b_hh_f    = (const float*)d_in[12];
    const float* w_ih_b    = (const float*)d_in[13];
    const float* w_hh_b    = (const float*)d_in[14];
    const float* b_ih_b    = (const float*)d_in[15];
    const float* b_hh_b    = (const float*)d_in[16];
    const float* nw        = (const float*)d_in[17];
    const float* nb        = (const float*)d_in[18];
    float* out = (float*)d_out;

    prep_kernel<<<64, 256>>>(w_dyn, w_ih_f, w_hh_f, w_ih_b, w_hh_b,
                             b_ih_f, b_hh_f, b_ih_b, b_hh_b);
    static_kernel<<<BB, 256>>>(x_static, w_s1, b_s1, w_s2, b_s2);
    fused_gemm_kernel<<<BB * TT / 32, 256>>>(x_dynamic, b_dyn);
    rnn_scan_kernel<<<256, 128>>>();
    cs_kernel<<<BB, 256>>>(order, nw, nb);
    out_kernel<<<BB, 256>>>(order, nw, out);
}

// round 3
// speedup vs baseline: 1.3017x; 1.3017x over previous
#include <cuda_runtime.h>
#include <cstddef>

#define BB 512
#define TT 200
#define SI 100
#define DI 68
#define HS 256
#define HD 128
#define NN 10000
#define DDIM 512   // 2*HD + HS

// ---------------- scratch (static device arrays; no runtime allocation) ----------------
__device__ float g_s[BB * HS];                 // static branch output [B,HS]
__device__ float g_xwf[BB * TT * HD];          // xw fwd -> overwritten by fwd hidden states
__device__ float g_xwb[BB * TT * HD];          // xw bwd -> overwritten by bwd hidden states
__device__ float g_cs[BB];                     // per-trial static dot + bias
__device__ float g_wdyn_t[DI * HD];            // w_dyn transposed [k][o]
__device__ float g_wihf_t[HD * HD];            // w_ih_f transposed [k][o]
__device__ float g_wihb_t[HD * HD];
__device__ float g_whhf_t[HD * HD];            // w_hh_f transposed [k][o]
__device__ float g_whhb_t[HD * HD];
__device__ float g_bxf[HD];                    // b_ih_f + b_hh_f
__device__ float g_bxb[HD];

// ---------------- prep: transposes + bias folds ----------------
__global__ void prep_kernel(const float* __restrict__ w_dyn,
                            const float* __restrict__ w_ih_f,
                            const float* __restrict__ w_hh_f,
                            const float* __restrict__ w_ih_b,
                            const float* __restrict__ w_hh_b,
                            const float* __restrict__ b_ih_f,
                            const float* __restrict__ b_hh_f,
                            const float* __restrict__ b_ih_b,
                            const float* __restrict__ b_hh_b) {
    int idx = blockIdx.x * blockDim.x + threadIdx.x;
    if (idx < HD * HD) {
        int o = idx / HD, k = idx % HD;
        g_wihf_t[k * HD + o] = w_ih_f[idx];
        g_wihb_t[k * HD + o] = w_ih_b[idx];
        g_whhf_t[k * HD + o] = w_hh_f[idx];
        g_whhb_t[k * HD + o] = w_hh_b[idx];
    }
    if (idx < HD * DI) {               // w_dyn is [HD,DI] row-major
        int o = idx / DI, i = idx % DI;
        g_wdyn_t[i * HD + o] = w_dyn[idx];
    }
    if (idx < HD) {
        g_bxf[idx] = b_ih_f[idx] + b_hh_f[idx];
        g_bxb[idx] = b_ih_b[idx] + b_hh_b[idx];
    }
}

// ---------------- static branch: 2-layer MLP, one block per trial ----------------
__global__ void static_kernel(const float* __restrict__ xs,
                              const float* __restrict__ w1, const float* __restrict__ b1,
                              const float* __restrict__ w2, const float* __restrict__ b2) {
    int b = blockIdx.x;
    int j = threadIdx.x;                // 256 threads, one per hidden unit
    __shared__ float xsh[SI];
    __shared__ float s1[HS];
    if (j < SI) xsh[j] = xs[b * SI + j];
    __syncthreads();
    float acc = b1[j];
    #pragma unroll 4
    for (int i = 0; i < SI; i++) acc += xsh[i] * w1[j * SI + i];
    s1[j] = fmaxf(acc, 0.f);
    __syncthreads();
    acc = b2[j];
    #pragma unroll 4
    for (int i = 0; i < HS; i++) acc += s1[i] * w2[j * HS + i];
    g_s[b * HS + j] = fmaxf(acc, 0.f);
}

// ---------------- fused: d = relu(x_dyn @ Wdyn^T + b); xw_{f,b} = d @ Wih^T + bx ----------------
// 256 threads = 8 warps; each warp independently owns 4 rows (b*T+t).
// Lane computes 4 rows x 4 output cols. No block barriers.
__global__ void __launch_bounds__(256) fused_gemm_kernel(const float* __restrict__ xd,
                                                         const float* __restrict__ bdyn) {
    __shared__ float xs[8][4 * DI];        // per-warp x rows (4 x 68)
    __shared__ float ds[8][4][HD];         // per-warp d rows (4 x 128)
    int w = threadIdx.x >> 5, lane = threadIdx.x & 31;
    size_t row0 = ((size_t)blockIdx.x * 8 + w) * 4;     // grid = 102400/32 = 3200

    const float* src = xd + row0 * DI;
    for (int i = lane; i < 4 * DI; i += 32) xs[w][i] = src[i];
    __syncwarp();

    // ---- stage 1: d tile ----
    {
        float4 bv = *(const float4*)&bdyn[4 * lane];
        float4 a0 = bv, a1 = bv, a2 = bv, a3 = bv;
        #pragma unroll 4
        for (int k = 0; k < DI; k++) {
            float4 wv = *(const float4*)&g_wdyn_t[k * HD + 4 * lane];
            float x0 = xs[w][0 * DI + k];
            float x1 = xs[w][1 * DI + k];
            float x2 = xs[w][2 * DI + k];
            float x3 = xs[w][3 * DI + k];
            a0.x += x0 * wv.x; a0.y += x0 * wv.y; a0.z += x0 * wv.z; a0.w += x0 * wv.w;
            a1.x += x1 * wv.x; a1.y += x1 * wv.y; a1.z += x1 * wv.z; a1.w += x1 * wv.w;
            a2.x += x2 * wv.x; a2.y += x2 * wv.y; a2.z += x2 * wv.z; a2.w += x2 * wv.w;
            a3.x += x3 * wv.x; a3.y += x3 * wv.y; a3.z += x3 * wv.z; a3.w += x3 * wv.w;
        }
        a0.x = fmaxf(a0.x, 0.f); a0.y = fmaxf(a0.y, 0.f); a0.z = fmaxf(a0.z, 0.f); a0.w = fmaxf(a0.w, 0.f);
        a1.x = fmaxf(a1.x, 0.f); a1.y = fmaxf(a1.y, 0.f); a1.z = fmaxf(a1.z, 0.f); a1.w = fmaxf(a1.w, 0.f);
        a2.x = fmaxf(a2.x, 0.f); a2.y = fmaxf(a2.y, 0.f); a2.z = fmaxf(a2.z, 0.f); a2.w = fmaxf(a2.w, 0.f);
        a3.x = fmaxf(a3.x, 0.f); a3.y = fmaxf(a3.y, 0.f); a3.z = fmaxf(a3.z, 0.f); a3.w = fmaxf(a3.w, 0.f);
        *(float4*)&ds[w][0][4 * lane] = a0;
        *(float4*)&ds[w][1][4 * lane] = a1;
        *(float4*)&ds[w][2][4 * lane] = a2;
        *(float4*)&ds[w][3][4 * lane] = a3;
    }
    __syncwarp();

    // ---- stage 2: dual GEMM over k=128 ----
    float4 bf4 = *(const float4*)&g_bxf[4 * lane];
    float4 bb4 = *(const float4*)&g_bxb[4 * lane];
    float4 f0 = bf4, f1 = bf4, f2 = bf4, f3 = bf4;
    float4 g0 = bb4, g1 = bb4, g2 = bb4, g3 = bb4;

    #pragma unroll 2
    for (int k = 0; k < HD; k += 4) {
        float4 d0 = *(const float4*)&ds[w][0][k];
        float4 d1 = *(const float4*)&ds[w][1][k];
        float4 d2 = *(const float4*)&ds[w][2][k];
        float4 d3 = *(const float4*)&ds[w][3][k];
        #pragma unroll
        for (int kk = 0; kk < 4; kk++) {
            float4 wf = *(const float4*)&g_wihf_t[(k + kk) * HD + 4 * lane];
            float4 wb = *(const float4*)&g_wihb_t[(k + kk) * HD + 4 * lane];
            float v0 = (kk == 0) ? d0.x : (kk == 1) ? d0.y : (kk == 2) ? d0.z : d0.w;
            float v1 = (kk == 0) ? d1.x : (kk == 1) ? d1.y : (kk == 2) ? d1.z : d1.w;
            float v2 = (kk == 0) ? d2.x : (kk == 1) ? d2.y : (kk == 2) ? d2.z : d2.w;
            float v3 = (kk == 0) ? d3.x : (kk == 1) ? d3.y : (kk == 2) ? d3.z : d3.w;
            f0.x += v0 * wf.x; f0.y += v0 * wf.y; f0.z += v0 * wf.z; f0.w += v0 * wf.w;
            f1.x += v1 * wf.x; f1.y += v1 * wf.y; f1.z += v1 * wf.z; f1.w += v1 * wf.w;
            f2.x += v2 * wf.x; f2.y += v2 * wf.y; f2.z += v2 * wf.z; f2.w += v2 * wf.w;
            f3.x += v3 * wf.x; f3.y += v3 * wf.y; f3.z += v3 * wf.z; f3.w += v3 * wf.w;
            g0.x += v0 * wb.x; g0.y += v0 * wb.y; g0.z += v0 * wb.z; g0.w += v0 * wb.w;
            g1.x += v1 * wb.x; g1.y += v1 * wb.y; g1.z += v1 * wb.z; g1.w += v1 * wb.w;
            g2.x += v2 * wb.x; g2.y += v2 * wb.y; g2.z += v2 * wb.z; g2.w += v2 * wb.w;
            g3.x += v3 * wb.x; g3.y += v3 * wb.y; g3.z += v3 * wb.z; g3.w += v3 * wb.w;
        }
    }

    size_t obase = row0 * HD + 4 * lane;
    *(float4*)&g_xwf[obase + 0 * HD] = f0;
    *(float4*)&g_xwf[obase + 1 * HD] = f1;
    *(float4*)&g_xwf[obase + 2 * HD] = f2;
    *(float4*)&g_xwf[obase + 3 * HD] = f3;
    *(float4*)&g_xwb[obase + 0 * HD] = g0;
    *(float4*)&g_xwb[obase + 1 * HD] = g1;
    *(float4*)&g_xwb[obase + 2 * HD] = g2;
    *(float4*)&g_xwb[obase + 3 * HD] = g3;
}

// ---------------- RNN scan: W cached in registers, 8 trials/block ----------------
// 128 blocks x 256 threads. Block b: dir = b&1, trials (b>>1)*8 .. +7.
// Warp w owns k-slice [16w,16w+16); lane owns 4 output cols (4l..4l+3).
// Each thread holds its 16x4 W tile in 64 registers (loaded once).
// Per step: partial sums (broadcast LDS of h) -> smem partials -> cross-warp
// reduction -> relu -> new h + in-place xw store. Two __syncthreads per step.
__global__ void __launch_bounds__(256) rnn_scan_kernel() {
    __shared__ float h_sm[8][HD];           // 4 KB
    __shared__ float part[8][8][HD];        // 32 KB: [kslice][trial][col]
    int tid = threadIdx.x;
    int w = tid >> 5, l = tid & 31;
    int dir = blockIdx.x & 1;
    int tbase = (blockIdx.x >> 1) * 8;
    const float* __restrict__ Wt = dir ? g_whhb_t : g_whhf_t;
    float* __restrict__ xw = dir ? g_xwb : g_xwf;

    // cache W tile: rows k = 16w..16w+15, cols 4l..4l+3
    float4 Wreg[16];
    #pragma unroll
    for (int j = 0; j < 16; j++)
        Wreg[j] = *(const float4*)&Wt[(w * 16 + j) * HD + 4 * l];

    // zero h (1024 floats, 4 per thread)
    *(float4*)&((float*)h_sm)[4 * tid] = make_float4(0.f, 0.f, 0.f, 0.f);

    // reduction-slot assignment: thread -> (trial rt, col-quad rc)
    int rt = tid >> 5;
    int rc = tid & 31;
    float* xw_rt = xw + (size_t)(tbase + rt) * TT * HD + 4 * rc;

    __syncthreads();

    for (int step = 0; step < TT; ++step) {
        int t = dir ? (TT - 1 - step) : step;

        // prefetch this thread's xw element for the reduction pass (hides DRAM/L2 lat)
        float4 xv = *(const float4*)&xw_rt[(size_t)t * HD];

        // ---- pass 1: partial GEMV over this warp's k-slice ----
        float4 acc[8];
        #pragma unroll
        for (int i = 0; i < 8; i++) acc[i] = make_float4(0.f, 0.f, 0.f, 0.f);

        #pragma unroll
        for (int q = 0; q < 4; q++) {
            float4 w0 = Wreg[4 * q + 0];
            float4 w1 = Wreg[4 * q + 1];
            float4 w2 = Wreg[4 * q + 2];
            float4 w3 = Wreg[4 * q + 3];
            #pragma unroll
            for (int tr = 0; tr < 8; tr++) {
                float4 hq = *(const float4*)&h_sm[tr][w * 16 + 4 * q];  // broadcast
                acc[tr].x += hq.x * w0.x + hq.y * w1.x + hq.z * w2.x + hq.w * w3.x;
                acc[tr].y += hq.x * w0.y + hq.y * w1.y + hq.z * w2.y + hq.w * w3.y;
                acc[tr].z += hq.x * w0.z + hq.y * w1.z + hq.z * w2.z + hq.w * w3.z;
                acc[tr].w += hq.x * w0.w + hq.y * w1.w + hq.z * w2.w + hq.w * w3.w;
            }
        }
        #pragma unroll
        for (int tr = 0; tr < 8; tr++)
            *(float4*)&part[w][tr][4 * l] = acc[tr];
        __syncthreads();   // h reads done; partials visible

        // ---- pass 2: reduce 8 k-slices for output (rt, 4rc..4rc+3) ----
        float4 s = *(const float4*)&part[0][rt][4 * rc];
        #pragma unroll
        for (int ww = 1; ww < 8; ww++) {
            float4 p = *(const float4*)&part[ww][rt][4 * rc];
            s.x += p.x; s.y += p.y; s.z += p.z; s.w += p.w;
        }
        s.x = fmaxf(s.x + xv.x, 0.f);
        s.y = fmaxf(s.y + xv.y, 0.f);
        s.z = fmaxf(s.z + xv.z, 0.f);
        s.w = fmaxf(s.w + xv.w, 0.f);
        *(float4*)&h_sm[rt][4 * rc] = s;
        *(float4*)&xw_rt[(size_t)t * HD] = s;   // in-place: becomes RNN output
        __syncthreads();   // new h visible before next step
    }
}

// ---------------- c_s[b] = <s[b], Wn[:256]> + bn ----------------
__global__ void cs_kernel(const int* __restrict__ order,
                          const float* __restrict__ nw,
                          const float* __restrict__ nb) {
    int b = blockIdx.x;
    int tid = threadIdx.x;               // 256
    int n = order[b];
    float v = g_s[b * HS + tid] * nw[(size_t)n * DDIM + tid];
    #pragma unroll
    for (int s = 16; s > 0; s >>= 1) v += __shfl_down_sync(0xffffffffu, v, s);
    __shared__ float partial[8];
    if ((tid & 31) == 0) partial[tid >> 5] = v;
    __syncthreads();
    if (tid == 0) {
        float sum = 0.f;
        #pragma unroll
        for (int i = 0; i < 8; i++) sum += partial[i];
        g_cs[b] = sum + nb[n];
    }
}

// ---------------- out[b,t] = relu(c_s[b] + <fwd, Wn[256:384]> + <bwd, Wn[384:512]>) ----------------
__global__ void out_kernel(const int* __restrict__ order,
                           const float* __restrict__ nw,
                           float* __restrict__ out) {
    int b = blockIdx.x;
    int tid = threadIdx.x;               // 256 = 8 warps
    int n = order[b];
    __shared__ float4 wsh[64];           // 256 floats: dynamic part of Wn
    if (tid < 64) wsh[tid] = *(const float4*)&nw[(size_t)n * DDIM + HS + 4 * tid];
    __syncthreads();
    float cs = g_cs[b];
    int w = tid >> 5, lane = tid & 31;
    float4 wf = wsh[lane];
    float4 wb = wsh[32 + lane];
    #pragma unroll 5
    for (int i = 0; i < 25; i++) {
        int t = w + 8 * i;
        size_t base = ((size_t)b * TT + t) * HD + 4 * lane;
        float4 fv = *(const float4*)&g_xwf[base];
        float4 bv = *(const float4*)&g_xwb[base];
        float acc = fv.x * wf.x + fv.y * wf.y + fv.z * wf.z + fv.w * wf.w
                  + bv.x * wb.x + bv.y * wb.y + bv.z * wb.z + bv.w * wb.w;
        #pragma unroll
        for (int s = 16; s > 0; s >>= 1) acc += __shfl_down_sync(0xffffffffu, acc, s);
        if (lane == 0) out[b * TT + t] = fmaxf(acc + cs, 0.f);
    }
}

// ---------------- launch ----------------
extern "C" void kernel_launch(void* const* d_in, const int* in_sizes, int n_in,
                              void* d_out, int out_size) {
    const float* x_static  = (const float*)d_in[0];
    const float* x_dynamic = (const float*)d_in[1];
    const int*   order     = (const int*)  d_in[2];
    const float* w_s1      = (const float*)d_in[3];
    const float* b_s1      = (const float*)d_in[4];
    const float* w_s2      = (const float*)d_in[5];
    const float* b_s2      = (const float*)d_in[6];
    const float* w_dyn     = (const float*)d_in[7];
    const float* b_dyn     = (const float*)d_in[8];
    const float* w_ih_f    = (const float*)d_in[9];
    const float* w_hh_f    = (const float*)d_in[10];
    const float* b_ih_f    = (const float*)d_in[11];
    const float* b_hh_f    = (const float*)d_in[12];
    const float* w_ih_b    = (const float*)d_in[13];
    const float* w_hh_b    = (const float*)d_in[14];
    const float* b_ih_b    = (const float*)d_in[15];
    const float* b_hh_b    = (const float*)d_in[16];
    const float* nw        = (const float*)d_in[17];
    const float* nb        = (const float*)d_in[18];
    float* out = (float*)d_out;

    prep_kernel<<<64, 256>>>(w_dyn, w_ih_f, w_hh_f, w_ih_b, w_hh_b,
                             b_ih_f, b_hh_f, b_ih_b, b_hh_b);
    static_kernel<<<BB, 256>>>(x_static, w_s1, b_s1, w_s2, b_s2);
    fused_gemm_kernel<<<BB * TT / 32, 256>>>(x_dynamic, b_dyn);
    rnn_scan_kernel<<<128, 256>>>();
    cs_kernel<<<BB, 256>>>(order, nw, nb);
    out_kernel<<<BB, 256>>>(order, nw, out);
}

// round 4
// speedup vs baseline: 1.3909x; 1.0685x over previous
#include <cuda_runtime.h>
#include <cstddef>
#include <cstdint>

#define BB 512
#define TT 200
#define SI 100
#define DI 68
#define HS 256
#define HD 128
#define NN 10000
#define DDIM 512   // 2*HD + HS

typedef unsigned long long ull;

// packed f32x2 helpers (sm_103a FFMA2 — only reachable via PTX)
#define FFMA2(D, A, B, C) \
    asm("fma.rn.f32x2 %0, %1, %2, %3;" : "=l"(D) : "l"(A), "l"(B), "l"(C))
#define PACKDUP(D, S) \
    asm("mov.b64 %0, {%1, %1};" : "=l"(D) : "r"(__float_as_uint(S)))
#define UNPACK2(LO, HI, V) \
    asm("mov.b64 {%0, %1}, %2;" : "=f"(LO), "=f"(HI) : "l"(V))

// ---------------- scratch (static device arrays; no runtime allocation) ----------------
__device__ float g_s[BB * HS];                 // static branch output [B,HS]
__device__ float g_xwf[BB * TT * HD];          // xw fwd -> overwritten by fwd hidden states
__device__ float g_xwb[BB * TT * HD];          // xw bwd -> overwritten by bwd hidden states
__device__ float g_cs[BB];                     // per-trial static dot + bias
__device__ float g_wdyn_t[DI * HD];            // w_dyn transposed [k][o]
__device__ float g_wihf_t[HD * HD];            // w_ih_f transposed [k][o]
__device__ float g_wihb_t[HD * HD];
__device__ float g_whhfp[64 * 256];            // Whh_f k-pair interleaved: [j][2c]=Wt[2j][c], [2c+1]=Wt[2j+1][c]
__device__ float g_whhbp[64 * 256];
__device__ float g_bxf[HD];                    // b_ih_f + b_hh_f
__device__ float g_bxb[HD];

// ---------------- prep: transposes + k-pair packing + bias folds ----------------
__global__ void prep_kernel(const float* __restrict__ w_dyn,
                            const float* __restrict__ w_ih_f,
                            const float* __restrict__ w_hh_f,
                            const float* __restrict__ w_ih_b,
                            const float* __restrict__ w_hh_b,
                            const float* __restrict__ b_ih_f,
                            const float* __restrict__ b_hh_f,
                            const float* __restrict__ b_ih_b,
                            const float* __restrict__ b_hh_b) {
    int idx = blockIdx.x * blockDim.x + threadIdx.x;
    if (idx < HD * HD) {
        int o = idx / HD, k = idx % HD;
        g_wihf_t[k * HD + o] = w_ih_f[idx];
        g_wihb_t[k * HD + o] = w_ih_b[idx];
    }
    if (idx < 64 * HD) {               // Whh k-pair packed layout
        int j = idx >> 7, c = idx & 127;     // Wt[k][c] = w_hh[c*HD + k]
        g_whhfp[j * 256 + 2 * c]     = w_hh_f[c * HD + 2 * j];
        g_whhfp[j * 256 + 2 * c + 1] = w_hh_f[c * HD + 2 * j + 1];
        g_whhbp[j * 256 + 2 * c]     = w_hh_b[c * HD + 2 * j];
        g_whhbp[j * 256 + 2 * c + 1] = w_hh_b[c * HD + 2 * j + 1];
    }
    if (idx < HD * DI) {               // w_dyn is [HD,DI] row-major
        int o = idx / DI, i = idx % DI;
        g_wdyn_t[i * HD + o] = w_dyn[idx];
    }
    if (idx < HD) {
        g_bxf[idx] = b_ih_f[idx] + b_hh_f[idx];
        g_bxb[idx] = b_ih_b[idx] + b_hh_b[idx];
    }
}

// ---------------- static branch: 2-layer MLP, one block per trial ----------------
__global__ void static_kernel(const float* __restrict__ xs,
                              const float* __restrict__ w1, const float* __restrict__ b1,
                              const float* __restrict__ w2, const float* __restrict__ b2) {
    int b = blockIdx.x;
    int j = threadIdx.x;                // 256 threads, one per hidden unit
    __shared__ float xsh[SI];
    __shared__ float s1[HS];
    if (j < SI) xsh[j] = xs[b * SI + j];
    __syncthreads();
    float acc = b1[j];
    #pragma unroll 4
    for (int i = 0; i < SI; i++) acc += xsh[i] * w1[j * SI + i];
    s1[j] = fmaxf(acc, 0.f);
    __syncthreads();
    acc = b2[j];
    #pragma unroll 4
    for (int i = 0; i < HS; i++) acc += s1[i] * w2[j * HS + i];
    g_s[b * HS + j] = fmaxf(acc, 0.f);
}

// ---------------- fused: d = relu(x_dyn @ Wdyn^T + b); xw_{f,b} = d @ Wih^T + bx ----------------
// 256 threads = 8 warps; each warp independently owns 4 rows (b*T+t).
// Lane computes 4 rows x 4 output cols, accumulators packed over col-pairs (FFMA2).
__global__ void __launch_bounds__(256) fused_gemm_kernel(const float* __restrict__ xd,
                                                         const float* __restrict__ bdyn) {
    __shared__ float xs[8][4 * DI];        // per-warp x rows (4 x 68)
    __shared__ float ds[8][4][HD];         // per-warp d rows (4 x 128)
    int w = threadIdx.x >> 5, lane = threadIdx.x & 31;
    size_t row0 = ((size_t)blockIdx.x * 8 + w) * 4;     // grid = 102400/32 = 3200

    const float* src = xd + row0 * DI;
    for (int i = lane; i < 4 * DI; i += 32) xs[w][i] = src[i];
    __syncwarp();

    // ---- stage 1: d tile (packed over col-pairs) ----
    {
        ulonglong2 bv = *(const ulonglong2*)&bdyn[4 * lane];
        ull a0p = bv.x, a0q = bv.y, a1p = bv.x, a1q = bv.y;
        ull a2p = bv.x, a2q = bv.y, a3p = bv.x, a3q = bv.y;
        #pragma unroll 4
        for (int k = 0; k < DI; k++) {
            ulonglong2 wv = *(const ulonglong2*)&g_wdyn_t[k * HD + 4 * lane];
            ull v0, v1, v2, v3;
            PACKDUP(v0, xs[w][0 * DI + k]);
            PACKDUP(v1, xs[w][1 * DI + k]);
            PACKDUP(v2, xs[w][2 * DI + k]);
            PACKDUP(v3, xs[w][3 * DI + k]);
            FFMA2(a0p, v0, wv.x, a0p); FFMA2(a0q, v0, wv.y, a0q);
            FFMA2(a1p, v1, wv.x, a1p); FFMA2(a1q, v1, wv.y, a1q);
            FFMA2(a2p, v2, wv.x, a2p); FFMA2(a2q, v2, wv.y, a2q);
            FFMA2(a3p, v3, wv.x, a3p); FFMA2(a3q, v3, wv.y, a3q);
        }
        float lo, hi;
        #define ST_RELU(r, P, Q) { \
            UNPACK2(lo, hi, P); \
            ds[w][r][4 * lane + 0] = fmaxf(lo, 0.f); \
            ds[w][r][4 * lane + 1] = fmaxf(hi, 0.f); \
            UNPACK2(lo, hi, Q); \
            ds[w][r][4 * lane + 2] = fmaxf(lo, 0.f); \
            ds[w][r][4 * lane + 3] = fmaxf(hi, 0.f); }
        ST_RELU(0, a0p, a0q)
        ST_RELU(1, a1p, a1q)
        ST_RELU(2, a2p, a2q)
        ST_RELU(3, a3p, a3q)
        #undef ST_RELU
    }
    __syncwarp();

    // ---- stage 2: dual GEMM over k=128 (packed over col-pairs) ----
    ulonglong2 bf2 = *(const ulonglong2*)&g_bxf[4 * lane];
    ulonglong2 bb2 = *(const ulonglong2*)&g_bxb[4 * lane];
    ull f0p = bf2.x, f0q = bf2.y, f1p = bf2.x, f1q = bf2.y;
    ull f2p = bf2.x, f2q = bf2.y, f3p = bf2.x, f3q = bf2.y;
    ull g0p = bb2.x, g0q = bb2.y, g1p = bb2.x, g1q = bb2.y;
    ull g2p = bb2.x, g2q = bb2.y, g3p = bb2.x, g3q = bb2.y;

    #pragma unroll 2
    for (int k = 0; k < HD; k += 4) {
        float4 d0 = *(const float4*)&ds[w][0][k];
        float4 d1 = *(const float4*)&ds[w][1][k];
        float4 d2 = *(const float4*)&ds[w][2][k];
        float4 d3 = *(const float4*)&ds[w][3][k];
        #pragma unroll
        for (int kk = 0; kk < 4; kk++) {
            ulonglong2 wf = *(const ulonglong2*)&g_wihf_t[(k + kk) * HD + 4 * lane];
            ulonglong2 wb = *(const ulonglong2*)&g_wihb_t[(k + kk) * HD + 4 * lane];
            float v0 = (kk == 0) ? d0.x : (kk == 1) ? d0.y : (kk == 2) ? d0.z : d0.w;
            float v1 = (kk == 0) ? d1.x : (kk == 1) ? d1.y : (kk == 2) ? d1.z : d1.w;
            float v2 = (kk == 0) ? d2.x : (kk == 1) ? d2.y : (kk == 2) ? d2.z : d2.w;
            float v3 = (kk == 0) ? d3.x : (kk == 1) ? d3.y : (kk == 2) ? d3.z : d3.w;
            ull p0, p1, p2, p3;
            PACKDUP(p0, v0); PACKDUP(p1, v1); PACKDUP(p2, v2); PACKDUP(p3, v3);
            FFMA2(f0p, p0, wf.x, f0p); FFMA2(f0q, p0, wf.y, f0q);
            FFMA2(f1p, p1, wf.x, f1p); FFMA2(f1q, p1, wf.y, f1q);
            FFMA2(f2p, p2, wf.x, f2p); FFMA2(f2q, p2, wf.y, f2q);
            FFMA2(f3p, p3, wf.x, f3p); FFMA2(f3q, p3, wf.y, f3q);
            FFMA2(g0p, p0, wb.x, g0p); FFMA2(g0q, p0, wb.y, g0q);
            FFMA2(g1p, p1, wb.x, g1p); FFMA2(g1q, p1, wb.y, g1q);
            FFMA2(g2p, p2, wb.x, g2p); FFMA2(g2q, p2, wb.y, g2q);
            FFMA2(g3p, p3, wb.x, g3p); FFMA2(g3q, p3, wb.y, g3q);
        }
    }

    size_t obase = row0 * HD + 4 * lane;
    *(ulonglong2*)&g_xwf[obase + 0 * HD] = make_ulonglong2(f0p, f0q);
    *(ulonglong2*)&g_xwf[obase + 1 * HD] = make_ulonglong2(f1p, f1q);
    *(ulonglong2*)&g_xwf[obase + 2 * HD] = make_ulonglong2(f2p, f2q);
    *(ulonglong2*)&g_xwf[obase + 3 * HD] = make_ulonglong2(f3p, f3q);
    *(ulonglong2*)&g_xwb[obase + 0 * HD] = make_ulonglong2(g0p, g0q);
    *(ulonglong2*)&g_xwb[obase + 1 * HD] = make_ulonglong2(g1p, g1q);
    *(ulonglong2*)&g_xwb[obase + 2 * HD] = make_ulonglong2(g2p, g2q);
    *(ulonglong2*)&g_xwb[obase + 3 * HD] = make_ulonglong2(g3p, g3q);
}

// ---------------- RNN scan: W (k-pair packed) in registers, FFMA2, 8 trials/block ----------------
// 128 blocks x 256 threads. Block b: dir = b&1, trials (b>>1)*8 .. +7.
// Warp w owns k-slice [16w,16w+16) = k-pairs [8w,8w+8); lane owns 4 output cols.
// Acc packed over (even-k, odd-k); combined with 1 FADD/col before partial store.
__global__ void __launch_bounds__(256) rnn_scan_kernel() {
    __shared__ float h_sm[8][HD];           // 4 KB
    __shared__ float part[8][8][HD];        // 32 KB: [kslice][trial][col]
    int tid = threadIdx.x;
    int w = tid >> 5, l = tid & 31;
    int dir = blockIdx.x & 1;
    int tbase = (blockIdx.x >> 1) * 8;
    const float* __restrict__ Wp = dir ? g_whhbp : g_whhfp;
    float* __restrict__ xw = dir ? g_xwb : g_xwf;

    // cache packed W tile: k-pairs 8w..8w+7, cols 4l..4l+3 (32 x f32x2 = 64 regs)
    ull Wa[8][4];
    #pragma unroll
    for (int jj = 0; jj < 8; jj++) {
        ulonglong2 p0 = *(const ulonglong2*)&Wp[(8 * w + jj) * 256 + 8 * l];
        ulonglong2 p1 = *(const ulonglong2*)&Wp[(8 * w + jj) * 256 + 8 * l + 4];
        Wa[jj][0] = p0.x; Wa[jj][1] = p0.y; Wa[jj][2] = p1.x; Wa[jj][3] = p1.y;
    }

    // zero h (1024 floats, 4 per thread)
    *(float4*)&((float*)h_sm)[4 * tid] = make_float4(0.f, 0.f, 0.f, 0.f);

    // reduction-slot assignment: thread -> (trial rt, col-quad rc)
    int rt = tid >> 5;
    int rc = tid & 31;
    float* xw_rt = xw + (size_t)(tbase + rt) * TT * HD + 4 * rc;

    __syncthreads();

    for (int step = 0; step < TT; ++step) {
        int t = dir ? (TT - 1 - step) : step;

        // prefetch this thread's xw element for the reduction pass
        float4 xv = *(const float4*)&xw_rt[(size_t)t * HD];

        // ---- pass 1: partial GEMV over this warp's k-slice, one trial at a time ----
        #pragma unroll
        for (int tr = 0; tr < 8; tr++) {
            ull a0 = 0, a1 = 0, a2 = 0, a3 = 0;
            #pragma unroll
            for (int q = 0; q < 4; q++) {
                ulonglong2 h4 = *(const ulonglong2*)&h_sm[tr][w * 16 + 4 * q];  // 2 k-pairs, broadcast
                FFMA2(a0, h4.x, Wa[2 * q][0], a0); FFMA2(a0, h4.y, Wa[2 * q + 1][0], a0);
                FFMA2(a1, h4.x, Wa[2 * q][1], a1); FFMA2(a1, h4.y, Wa[2 * q + 1][1], a1);
                FFMA2(a2, h4.x, Wa[2 * q][2], a2); FFMA2(a2, h4.y, Wa[2 * q + 1][2], a2);
                FFMA2(a3, h4.x, Wa[2 * q][3], a3); FFMA2(a3, h4.y, Wa[2 * q + 1][3], a3);
            }
            float lo0, hi0, lo1, hi1, lo2, hi2, lo3, hi3;
            UNPACK2(lo0, hi0, a0);
            UNPACK2(lo1, hi1, a1);
            UNPACK2(lo2, hi2, a2);
            UNPACK2(lo3, hi3, a3);
            *(float4*)&part[w][tr][4 * l] =
                make_float4(lo0 + hi0, lo1 + hi1, lo2 + hi2, lo3 + hi3);
        }
        __syncthreads();   // h reads done; partials visible

        // ---- pass 2: reduce 8 k-slices for output (rt, 4rc..4rc+3) ----
        float4 s = *(const float4*)&part[0][rt][4 * rc];
        #pragma unroll
        for (int ww = 1; ww < 8; ww++) {
            float4 p = *(const float4*)&part[ww][rt][4 * rc];
            s.x += p.x; s.y += p.y; s.z += p.z; s.w += p.w;
        }
        s.x = fmaxf(s.x + xv.x, 0.f);
        s.y = fmaxf(s.y + xv.y, 0.f);
        s.z = fmaxf(s.z + xv.z, 0.f);
        s.w = fmaxf(s.w + xv.w, 0.f);
        *(float4*)&h_sm[rt][4 * rc] = s;
        *(float4*)&xw_rt[(size_t)t * HD] = s;   // in-place: becomes RNN output
        __syncthreads();   // new h visible before next step
    }
}

// ---------------- c_s[b] = <s[b], Wn[:256]> + bn ----------------
__global__ void cs_kernel(const int* __restrict__ order,
                          const float* __restrict__ nw,
                          const float* __restrict__ nb) {
    int b = blockIdx.x;
    int tid = threadIdx.x;               // 256
    int n = order[b];
    float v = g_s[b * HS + tid] * nw[(size_t)n * DDIM + tid];
    #pragma unroll
    for (int s = 16; s > 0; s >>= 1) v += __shfl_down_sync(0xffffffffu, v, s);
    __shared__ float partial[8];
    if ((tid & 31) == 0) partial[tid >> 5] = v;
    __syncthreads();
    if (tid == 0) {
        float sum = 0.f;
        #pragma unroll
        for (int i = 0; i < 8; i++) sum += partial[i];
        g_cs[b] = sum + nb[n];
    }
}

// ---------------- out[b,t] = relu(c_s[b] + <fwd, Wn[256:384]> + <bwd, Wn[384:512]>) ----------------
__global__ void out_kernel(const int* __restrict__ order,
                           const float* __restrict__ nw,
                           float* __restrict__ out) {
    int b = blockIdx.x;
    int tid = threadIdx.x;               // 256 = 8 warps
    int n = order[b];
    __shared__ float4 wsh[64];           // 256 floats: dynamic part of Wn
    if (tid < 64) wsh[tid] = *(const float4*)&nw[(size_t)n * DDIM + HS + 4 * tid];
    __syncthreads();
    float cs = g_cs[b];
    int w = tid >> 5, lane = tid & 31;
    float4 wf = wsh[lane];
    float4 wb = wsh[32 + lane];
    #pragma unroll 5
    for (int i = 0; i < 25; i++) {
        int t = w + 8 * i;
        size_t base = ((size_t)b * TT + t) * HD + 4 * lane;
        float4 fv = *(const float4*)&g_xwf[base];
        float4 bv = *(const float4*)&g_xwb[base];
        float acc = fv.x * wf.x + fv.y * wf.y + fv.z * wf.z + fv.w * wf.w
                  + bv.x * wb.x + bv.y * wb.y + bv.z * wb.z + bv.w * wb.w;
        #pragma unroll
        for (int s = 16; s > 0; s >>= 1) acc += __shfl_down_sync(0xffffffffu, acc, s);
        if (lane == 0) out[b * TT + t] = fmaxf(acc + cs, 0.f);
    }
}

// ---------------- launch ----------------
extern "C" void kernel_launch(void* const* d_in, const int* in_sizes, int n_in,
                              void* d_out, int out_size) {
    const float* x_static  = (const float*)d_in[0];
    const float* x_dynamic = (const float*)d_in[1];
    const int*   order     = (const int*)  d_in[2];
    const float* w_s1      = (const float*)d_in[3];
    const float* b_s1      = (const float*)d_in[4];
    const float* w_s2      = (const float*)d_in[5];
    const float* b_s2      = (const float*)d_in[6];
    const float* w_dyn     = (const float*)d_in[7];
    const float* b_dyn     = (const float*)d_in[8];
    const float* w_ih_f    = (const float*)d_in[9];
    const float* w_hh_f    = (const float*)d_in[10];
    const float* b_ih_f    = (const float*)d_in[11];
    const float* b_hh_f    = (const float*)d_in[12];
    const float* w_ih_b    = (const float*)d_in[13];
    const float* w_hh_b    = (const float*)d_in[14];
    const float* b_ih_b    = (const float*)d_in[15];
    const float* b_hh_b    = (const float*)d_in[16];
    const float* nw        = (const float*)d_in[17];
    const float* nb        = (const float*)d_in[18];
    float* out = (float*)d_out;

    prep_kernel<<<64, 256>>>(w_dyn, w_ih_f, w_hh_f, w_ih_b, w_hh_b,
                             b_ih_f, b_hh_f, b_ih_b, b_hh_b);
    static_kernel<<<BB, 256>>>(x_static, w_s1, b_s1, w_s2, b_s2);
    fused_gemm_kernel<<<BB * TT / 32, 256>>>(x_dynamic, b_dyn);
    rnn_scan_kernel<<<128, 256>>>();
    cs_kernel<<<BB, 256>>>(order, nw, nb);
    out_kernel<<<BB, 256>>>(order, nw, out);
}

// round 5
// speedup vs baseline: 1.4695x; 1.0565x over previous
#include <cuda_runtime.h>
#include <cstddef>
#include <cstdint>

#define BB 512
#define TT 200
#define SI 100
#define DI 68
#define HS 256
#define HD 128
#define NN 10000
#define DDIM 512   // 2*HD + HS

typedef unsigned long long ull;

// packed f32x2 helpers (sm_103a FFMA2 — only reachable via PTX)
#define FFMA2(D, A, B, C) \
    asm("fma.rn.f32x2 %0, %1, %2, %3;" : "=l"(D) : "l"(A), "l"(B), "l"(C))
#define PACKDUP(D, S) \
    asm("mov.b64 %0, {%1, %1};" : "=l"(D) : "r"(__float_as_uint(S)))
#define UNPACK2(LO, HI, V) \
    asm("mov.b64 {%0, %1}, %2;" : "=f"(LO), "=f"(HI) : "l"(V))

// ---------------- scratch (static device arrays; no runtime allocation) ----------------
__device__ float g_s[BB * HS];                 // static branch output [B,HS]
__device__ float g_xwf[BB * TT * HD];          // xw fwd (pre-activation input proj)
__device__ float g_xwb[BB * TT * HD];          // xw bwd
__device__ float g_dotf[BB * TT];              // per-(b,t) fwd routed dot
__device__ float g_dotb[BB * TT];              // per-(b,t) bwd routed dot
__device__ float g_cs[BB];                     // per-trial static dot + bias
__device__ float g_wdyn_t[DI * HD];            // w_dyn transposed [k][o]
__device__ float g_wihf_t[HD * HD];            // w_ih_f transposed [k][o]
__device__ float g_wihb_t[HD * HD];
__device__ float g_whhfp[64 * 256];            // Whh_f k-pair interleaved
__device__ float g_whhbp[64 * 256];
__device__ float g_bxf[HD];                    // b_ih_f + b_hh_f
__device__ float g_bxb[HD];

// ---------------- prep: transposes + k-pair packing + bias folds ----------------
__global__ void prep_kernel(const float* __restrict__ w_dyn,
                            const float* __restrict__ w_ih_f,
                            const float* __restrict__ w_hh_f,
                            const float* __restrict__ w_ih_b,
                            const float* __restrict__ w_hh_b,
                            const float* __restrict__ b_ih_f,
                            const float* __restrict__ b_hh_f,
                            const float* __restrict__ b_ih_b,
                            const float* __restrict__ b_hh_b) {
    int idx = blockIdx.x * blockDim.x + threadIdx.x;
    if (idx < HD * HD) {
        int o = idx / HD, k = idx % HD;
        g_wihf_t[k * HD + o] = w_ih_f[idx];
        g_wihb_t[k * HD + o] = w_ih_b[idx];
    }
    if (idx < 64 * HD) {               // Whh k-pair packed layout
        int j = idx >> 7, c = idx & 127;     // Wt[k][c] = w_hh[c*HD + k]
        g_whhfp[j * 256 + 2 * c]     = w_hh_f[c * HD + 2 * j];
        g_whhfp[j * 256 + 2 * c + 1] = w_hh_f[c * HD + 2 * j + 1];
        g_whhbp[j * 256 + 2 * c]     = w_hh_b[c * HD + 2 * j];
        g_whhbp[j * 256 + 2 * c + 1] = w_hh_b[c * HD + 2 * j + 1];
    }
    if (idx < HD * DI) {               // w_dyn is [HD,DI] row-major
        int o = idx / DI, i = idx % DI;
        g_wdyn_t[i * HD + o] = w_dyn[idx];
    }
    if (idx < HD) {
        g_bxf[idx] = b_ih_f[idx] + b_hh_f[idx];
        g_bxb[idx] = b_ih_b[idx] + b_hh_b[idx];
    }
}

// ---------------- static branch: 2-layer MLP, one block per trial ----------------
__global__ void static_kernel(const float* __restrict__ xs,
                              const float* __restrict__ w1, const float* __restrict__ b1,
                              const float* __restrict__ w2, const float* __restrict__ b2) {
    int b = blockIdx.x;
    int j = threadIdx.x;                // 256 threads, one per hidden unit
    __shared__ float xsh[SI];
    __shared__ float s1[HS];
    if (j < SI) xsh[j] = xs[b * SI + j];
    __syncthreads();
    float acc = b1[j];
    #pragma unroll 4
    for (int i = 0; i < SI; i++) acc += xsh[i] * w1[j * SI + i];
    s1[j] = fmaxf(acc, 0.f);
    __syncthreads();
    acc = b2[j];
    #pragma unroll 4
    for (int i = 0; i < HS; i++) acc += s1[i] * w2[j * HS + i];
    g_s[b * HS + j] = fmaxf(acc, 0.f);
}

// ---------------- fused: d = relu(x_dyn @ Wdyn^T + b); xw_{f,b} = d @ Wih^T + bx ----------------
__global__ void __launch_bounds__(256) fused_gemm_kernel(const float* __restrict__ xd,
                                                         const float* __restrict__ bdyn) {
    __shared__ float xs[8][4 * DI];        // per-warp x rows (4 x 68)
    __shared__ float ds[8][4][HD];         // per-warp d rows (4 x 128)
    int w = threadIdx.x >> 5, lane = threadIdx.x & 31;
    size_t row0 = ((size_t)blockIdx.x * 8 + w) * 4;     // grid = 102400/32 = 3200

    const float* src = xd + row0 * DI;
    for (int i = lane; i < 4 * DI; i += 32) xs[w][i] = src[i];
    __syncwarp();

    // ---- stage 1: d tile (packed over col-pairs) ----
    {
        ulonglong2 bv = *(const ulonglong2*)&bdyn[4 * lane];
        ull a0p = bv.x, a0q = bv.y, a1p = bv.x, a1q = bv.y;
        ull a2p = bv.x, a2q = bv.y, a3p = bv.x, a3q = bv.y;
        #pragma unroll 4
        for (int k = 0; k < DI; k++) {
            ulonglong2 wv = *(const ulonglong2*)&g_wdyn_t[k * HD + 4 * lane];
            ull v0, v1, v2, v3;
            PACKDUP(v0, xs[w][0 * DI + k]);
            PACKDUP(v1, xs[w][1 * DI + k]);
            PACKDUP(v2, xs[w][2 * DI + k]);
            PACKDUP(v3, xs[w][3 * DI + k]);
            FFMA2(a0p, v0, wv.x, a0p); FFMA2(a0q, v0, wv.y, a0q);
            FFMA2(a1p, v1, wv.x, a1p); FFMA2(a1q, v1, wv.y, a1q);
            FFMA2(a2p, v2, wv.x, a2p); FFMA2(a2q, v2, wv.y, a2q);
            FFMA2(a3p, v3, wv.x, a3p); FFMA2(a3q, v3, wv.y, a3q);
        }
        float lo, hi;
        #define ST_RELU(r, P, Q) { \
            UNPACK2(lo, hi, P); \
            ds[w][r][4 * lane + 0] = fmaxf(lo, 0.f); \
            ds[w][r][4 * lane + 1] = fmaxf(hi, 0.f); \
            UNPACK2(lo, hi, Q); \
            ds[w][r][4 * lane + 2] = fmaxf(lo, 0.f); \
            ds[w][r][4 * lane + 3] = fmaxf(hi, 0.f); }
        ST_RELU(0, a0p, a0q)
        ST_RELU(1, a1p, a1q)
        ST_RELU(2, a2p, a2q)
        ST_RELU(3, a3p, a3q)
        #undef ST_RELU
    }
    __syncwarp();

    // ---- stage 2: dual GEMM over k=128 (packed over col-pairs) ----
    ulonglong2 bf2 = *(const ulonglong2*)&g_bxf[4 * lane];
    ulonglong2 bb2 = *(const ulonglong2*)&g_bxb[4 * lane];
    ull f0p = bf2.x, f0q = bf2.y, f1p = bf2.x, f1q = bf2.y;
    ull f2p = bf2.x, f2q = bf2.y, f3p = bf2.x, f3q = bf2.y;
    ull g0p = bb2.x, g0q = bb2.y, g1p = bb2.x, g1q = bb2.y;
    ull g2p = bb2.x, g2q = bb2.y, g3p = bb2.x, g3q = bb2.y;

    #pragma unroll 2
    for (int k = 0; k < HD; k += 4) {
        float4 d0 = *(const float4*)&ds[w][0][k];
        float4 d1 = *(const float4*)&ds[w][1][k];
        float4 d2 = *(const float4*)&ds[w][2][k];
        float4 d3 = *(const float4*)&ds[w][3][k];
        #pragma unroll
        for (int kk = 0; kk < 4; kk++) {
            ulonglong2 wf = *(const ulonglong2*)&g_wihf_t[(k + kk) * HD + 4 * lane];
            ulonglong2 wb = *(const ulonglong2*)&g_wihb_t[(k + kk) * HD + 4 * lane];
            float v0 = (kk == 0) ? d0.x : (kk == 1) ? d0.y : (kk == 2) ? d0.z : d0.w;
            float v1 = (kk == 0) ? d1.x : (kk == 1) ? d1.y : (kk == 2) ? d1.z : d1.w;
            float v2 = (kk == 0) ? d2.x : (kk == 1) ? d2.y : (kk == 2) ? d2.z : d2.w;
            float v3 = (kk == 0) ? d3.x : (kk == 1) ? d3.y : (kk == 2) ? d3.z : d3.w;
            ull p0, p1, p2, p3;
            PACKDUP(p0, v0); PACKDUP(p1, v1); PACKDUP(p2, v2); PACKDUP(p3, v3);
            FFMA2(f0p, p0, wf.x, f0p); FFMA2(f0q, p0, wf.y, f0q);
            FFMA2(f1p, p1, wf.x, f1p); FFMA2(f1q, p1, wf.y, f1q);
            FFMA2(f2p, p2, wf.x, f2p); FFMA2(f2q, p2, wf.y, f2q);
            FFMA2(f3p, p3, wf.x, f3p); FFMA2(f3q, p3, wf.y, f3q);
            FFMA2(g0p, p0, wb.x, g0p); FFMA2(g0q, p0, wb.y, g0q);
            FFMA2(g1p, p1, wb.x, g1p); FFMA2(g1q, p1, wb.y, g1q);
            FFMA2(g2p, p2, wb.x, g2p); FFMA2(g2q, p2, wb.y, g2q);
            FFMA2(g3p, p3, wb.x, g3p); FFMA2(g3q, p3, wb.y, g3q);
        }
    }

    size_t obase = row0 * HD + 4 * lane;
    *(ulonglong2*)&g_xwf[obase + 0 * HD] = make_ulonglong2(f0p, f0q);
    *(ulonglong2*)&g_xwf[obase + 1 * HD] = make_ulonglong2(f1p, f1q);
    *(ulonglong2*)&g_xwf[obase + 2 * HD] = make_ulonglong2(f2p, f2q);
    *(ulonglong2*)&g_xwf[obase + 3 * HD] = make_ulonglong2(f3p, f3q);
    *(ulonglong2*)&g_xwb[obase + 0 * HD] = make_ulonglong2(g0p, g0q);
    *(ulonglong2*)&g_xwb[obase + 1 * HD] = make_ulonglong2(g1p, g1q);
    *(ulonglong2*)&g_xwb[obase + 2 * HD] = make_ulonglong2(g2p, g2q);
    *(ulonglong2*)&g_xwb[obase + 3 * HD] = make_ulonglong2(g3p, g3q);
}

// ---------------- RNN scan + fused routed dot ----------------
// grid = 256 blocks, 2 co-resident per SM. Block: dir = b&1, trials (b>>1)*4..+3.
// Warp w owns k-pairs [8w,8w+8); lane owns 4 output cols. W tile in 64 regs.
// pass2 slot: trial rt = tid>>6, cols 2rc..2rc+1 (rc = tid&63).
// Hidden state h never leaves smem: the routed dot h.wn is computed per step.
__global__ void __launch_bounds__(256, 2) rnn_scan_kernel(const int* __restrict__ order,
                                                          const float* __restrict__ nw) {
    __shared__ float h_sm[4][HD];           // 2 KB
    __shared__ float part[8][4][HD];        // 16 KB: [kslice][trial][col]
    __shared__ float wn_sm[4][HD];          // 2 KB: routed weights for this dir
    __shared__ float dsum[4][2];
    int tid = threadIdx.x;
    int w = tid >> 5, l = tid & 31;
    int dir = blockIdx.x & 1;
    int tbase = (blockIdx.x >> 1) * 4;
    const float* __restrict__ Wp = dir ? g_whhbp : g_whhfp;
    const float* __restrict__ xw = dir ? g_xwb : g_xwf;
    float* __restrict__ dot = dir ? g_dotb : g_dotf;

    // cache packed W tile: k-pairs 8w..8w+7, cols 4l..4l+3 (32 x f32x2 = 64 regs)
    ull Wa[8][4];
    #pragma unroll
    for (int jj = 0; jj < 8; jj++) {
        ulonglong2 p0 = *(const ulonglong2*)&Wp[(8 * w + jj) * 256 + 8 * l];
        ulonglong2 p1 = *(const ulonglong2*)&Wp[(8 * w + jj) * 256 + 8 * l + 4];
        Wa[jj][0] = p0.x; Wa[jj][1] = p0.y; Wa[jj][2] = p1.x; Wa[jj][3] = p1.y;
    }

    // load routed weights for 4 trials (2 floats per thread)
    {
        int tr = tid >> 6, c = (tid & 63) * 2;
        int n = order[tbase + tr];
        const float* wsrc = nw + (size_t)n * DDIM + HS + dir * HD + c;
        wn_sm[tr][c]     = wsrc[0];
        wn_sm[tr][c + 1] = wsrc[1];
    }

    // zero h (512 floats, 2 per thread)
    *(float2*)&((float*)h_sm)[2 * tid] = make_float2(0.f, 0.f);

    int rt = tid >> 6;
    int rc = tid & 63;
    const float* xw_rt = xw + (size_t)(tbase + rt) * TT * HD + 2 * rc;

    __syncthreads();
    float2 wn2 = *(const float2*)&wn_sm[rt][2 * rc];

    for (int step = 0; step < TT; ++step) {
        int t = dir ? (TT - 1 - step) : step;

        // prefetch xw for the reduction pass
        float2 xv = *(const float2*)&xw_rt[(size_t)t * HD];

        // ---- pass 1: partial GEMV over this warp's k-slice, per trial ----
        #pragma unroll
        for (int tr = 0; tr < 4; tr++) {
            ull a0 = 0, a1 = 0, a2 = 0, a3 = 0;
            #pragma unroll
            for (int q = 0; q < 4; q++) {
                ulonglong2 h4 = *(const ulonglong2*)&h_sm[tr][w * 16 + 4 * q];  // broadcast
                FFMA2(a0, h4.x, Wa[2 * q][0], a0); FFMA2(a0, h4.y, Wa[2 * q + 1][0], a0);
                FFMA2(a1, h4.x, Wa[2 * q][1], a1); FFMA2(a1, h4.y, Wa[2 * q + 1][1], a1);
                FFMA2(a2, h4.x, Wa[2 * q][2], a2); FFMA2(a2, h4.y, Wa[2 * q + 1][2], a2);
                FFMA2(a3, h4.x, Wa[2 * q][3], a3); FFMA2(a3, h4.y, Wa[2 * q + 1][3], a3);
            }
            float lo0, hi0, lo1, hi1, lo2, hi2, lo3, hi3;
            UNPACK2(lo0, hi0, a0);
            UNPACK2(lo1, hi1, a1);
            UNPACK2(lo2, hi2, a2);
            UNPACK2(lo3, hi3, a3);
            *(float4*)&part[w][tr][4 * l] =
                make_float4(lo0 + hi0, lo1 + hi1, lo2 + hi2, lo3 + hi3);
        }
        __syncthreads();   // h reads done; partials visible

        // ---- pass 2: reduce 8 k-slices for (rt, cols 2rc..2rc+1) ----
        float2 s = *(const float2*)&part[0][rt][2 * rc];
        #pragma unroll
        for (int ww = 1; ww < 8; ww++) {
            float2 p = *(const float2*)&part[ww][rt][2 * rc];
            s.x += p.x; s.y += p.y;
        }
        s.x = fmaxf(s.x + xv.x, 0.f);
        s.y = fmaxf(s.y + xv.y, 0.f);
        *(float2*)&h_sm[rt][2 * rc] = s;

        // fused routed dot: h . wn  (64 threads per trial = 2 warps)
        float dp = s.x * wn2.x + s.y * wn2.y;
        #pragma unroll
        for (int off = 16; off > 0; off >>= 1)
            dp += __shfl_down_sync(0xffffffffu, dp, off);
        if (l == 0) dsum[rt][(tid >> 5) & 1] = dp;
        __syncthreads();   // new h + dsum visible

        if (tid < 4)
            dot[(size_t)(tbase + tid) * TT + t] = dsum[tid][0] + dsum[tid][1];
    }
}

// ---------------- c_s[b] = <s[b], Wn[:256]> + bn ----------------
__global__ void cs_kernel(const int* __restrict__ order,
                          const float* __restrict__ nw,
                          const float* __restrict__ nb) {
    int b = blockIdx.x;
    int tid = threadIdx.x;               // 256
    int n = order[b];
    float v = g_s[b * HS + tid] * nw[(size_t)n * DDIM + tid];
    #pragma unroll
    for (int s = 16; s > 0; s >>= 1) v += __shfl_down_sync(0xffffffffu, v, s);
    __shared__ float partial[8];
    if ((tid & 31) == 0) partial[tid >> 5] = v;
    __syncthreads();
    if (tid == 0) {
        float sum = 0.f;
        #pragma unroll
        for (int i = 0; i < 8; i++) sum += partial[i];
        g_cs[b] = sum + nb[n];
    }
}

// ---------------- out[b,t] = relu(cs[b] + dotf[b,t] + dotb[b,t]) ----------------
__global__ void combine_kernel(float* __restrict__ out) {
    int i = blockIdx.x * 256 + threadIdx.x;    // 102400 total
    int b = i / TT;
    out[i] = fmaxf(g_cs[b] + g_dotf[i] + g_dotb[i], 0.f);
}

// ---------------- launch ----------------
extern "C" void kernel_launch(void* const* d_in, const int* in_sizes, int n_in,
                              void* d_out, int out_size) {
    const float* x_static  = (const float*)d_in[0];
    const float* x_dynamic = (const float*)d_in[1];
    const int*   order     = (const int*)  d_in[2];
    const float* w_s1      = (const float*)d_in[3];
    const float* b_s1      = (const float*)d_in[4];
    const float* w_s2      = (const float*)d_in[5];
    const float* b_s2      = (const float*)d_in[6];
    const float* w_dyn     = (const float*)d_in[7];
    const float* b_dyn     = (const float*)d_in[8];
    const float* w_ih_f    = (const float*)d_in[9];
    const float* w_hh_f    = (const float*)d_in[10];
    const float* b_ih_f    = (const float*)d_in[11];
    const float* b_hh_f    = (const float*)d_in[12];
    const float* w_ih_b    = (const float*)d_in[13];
    const float* w_hh_b    = (const float*)d_in[14];
    const float* b_ih_b    = (const float*)d_in[15];
    const float* b_hh_b    = (const float*)d_in[16];
    const float* nw        = (const float*)d_in[17];
    const float* nb        = (const float*)d_in[18];
    float* out = (float*)d_out;

    prep_kernel<<<64, 256>>>(w_dyn, w_ih_f, w_hh_f, w_ih_b, w_hh_b,
                             b_ih_f, b_hh_f, b_ih_b, b_hh_b);
    static_kernel<<<BB, 256>>>(x_static, w_s1, b_s1, w_s2, b_s2);
    fused_gemm_kernel<<<BB * TT / 32, 256>>>(x_dynamic, b_dyn);
    rnn_scan_kernel<<<256, 256>>>(order, nw);
    cs_kernel<<<BB, 256>>>(order, nw, nb);
    combine_kernel<<<BB * TT / 256, 256>>>(out);
}